// round 1
// baseline (speedup 1.0000x reference)
#include <cuda_runtime.h>

// SpatialTransformer3D: batched 3D trilinear sampling.
// image: (B=2, H=128, W=128, D=128, C=4) f32
// transformation: (B=2, 128, 128, 128, 3) f32
// out: (B=2, 128, 128, 128, 4) f32
//
// Reference semantics:
//   grid[i,j,k] = (xl[j], yl[i], zl[k]) with l = linspace(-1,1,128)
//   coords = transformation * grid (elementwise)
//   x = 0.5*(cx+1)*W ; y = 0.5*(cy+1)*H ; z = 0.5*(cz+1)*D
//   x0=floor, x1=clip(x0+1), x0=clip(x0) ; weights dx = x1 - x (clipped corner!)
//   gather img[y, x, z]  (note index order y,x,z)

__global__ __launch_bounds__(256) void st3d_kernel(
    const float* __restrict__ img,
    const float* __restrict__ trans,
    float* __restrict__ out,
    int total)
{
    int idx = blockIdx.x * blockDim.x + threadIdx.x;
    if (idx >= total) return;

    // idx = ((b*128 + i)*128 + j)*128 + k   (i:OH/y, j:OW/x, k:OD/z)
    int k = idx & 127;
    int j = (idx >> 7) & 127;
    int i = (idx >> 14) & 127;
    int b = idx >> 21;

    const float step = 2.0f / 127.0f;
    float xl = -1.0f + (float)j * step;
    float yl = -1.0f + (float)i * step;
    float zl = -1.0f + (float)k * step;

    const float* t = trans + (size_t)idx * 3;
    float cx = __ldg(&t[0]) * xl;
    float cy = __ldg(&t[1]) * yl;
    float cz = __ldg(&t[2]) * zl;

    float x = 0.5f * (cx + 1.0f) * 128.0f;
    float y = 0.5f * (cy + 1.0f) * 128.0f;
    float z = 0.5f * (cz + 1.0f) * 128.0f;

    int x0 = (int)floorf(x);
    int y0 = (int)floorf(y);
    int z0 = (int)floorf(z);
    int x1 = min(max(x0 + 1, 0), 127);
    int y1 = min(max(y0 + 1, 0), 127);
    int z1 = min(max(z0 + 1, 0), 127);
    x0 = min(max(x0, 0), 127);
    y0 = min(max(y0, 0), 127);
    z0 = min(max(z0, 0), 127);

    float dx = (float)x1 - x;
    float dy = (float)y1 - y;
    float dz = (float)z1 - z;
    float ex = 1.0f - dx;
    float ey = 1.0f - dy;
    float ez = 1.0f - dz;

    // image as float4 (C=4): element (b, y, x, z) at b*2097152 + (y<<14 | x<<7 | z)
    const float4* imgb = reinterpret_cast<const float4*>(img) + (size_t)b * 2097152;

    int base00 = (y0 << 14) | (x0 << 7);   // (y0, x0)
    int base10 = (y1 << 14) | (x0 << 7);   // (y1, x0)
    int base01 = (y0 << 14) | (x1 << 7);   // (y0, x1)
    int base11 = (y1 << 14) | (x1 << 7);   // (y1, x1)

    float4 g000 = __ldg(&imgb[base00 | z0]);
    float4 g100 = __ldg(&imgb[base10 | z0]);
    float4 g010 = __ldg(&imgb[base01 | z0]);
    float4 g110 = __ldg(&imgb[base11 | z0]);
    float4 g001 = __ldg(&imgb[base00 | z1]);
    float4 g101 = __ldg(&imgb[base10 | z1]);
    float4 g011 = __ldg(&imgb[base01 | z1]);
    float4 g111 = __ldg(&imgb[base11 | z1]);

    float w000 = dz * dx * dy;
    float w100 = dz * dx * ey;
    float w010 = dz * ex * dy;
    float w110 = dz * ex * ey;
    float w001 = ez * dx * dy;
    float w101 = ez * dx * ey;
    float w011 = ez * ex * dy;
    float w111 = ez * ex * ey;

    float4 r;
    r.x = w000*g000.x + w100*g100.x + w010*g010.x + w110*g110.x
        + w001*g001.x + w101*g101.x + w011*g011.x + w111*g111.x;
    r.y = w000*g000.y + w100*g100.y + w010*g010.y + w110*g110.y
        + w001*g001.y + w101*g101.y + w011*g011.y + w111*g111.y;
    r.z = w000*g000.z + w100*g100.z + w010*g010.z + w110*g110.z
        + w001*g001.z + w101*g101.z + w011*g011.z + w111*g111.z;
    r.w = w000*g000.w + w100*g100.w + w010*g010.w + w110*g110.w
        + w001*g001.w + w101*g101.w + w011*g011.w + w111*g111.w;

    reinterpret_cast<float4*>(out)[idx] = r;
}

extern "C" void kernel_launch(void* const* d_in, const int* in_sizes, int n_in,
                              void* d_out, int out_size)
{
    const float* img = (const float*)d_in[0];
    const float* trans = (const float*)d_in[1];
    float* out = (float*)d_out;

    int total = out_size / 4;  // voxels = 2*128^3 = 4194304
    int threads = 256;
    int blocks = (total + threads - 1) / threads;
    st3d_kernel<<<blocks, threads>>>(img, trans, out, total);
}

// round 2
// speedup vs baseline: 1.3667x; 1.3667x over previous
#include <cuda_runtime.h>

// SpatialTransformer3D: batched 3D trilinear sampling, 2 lanes per voxel.
// Lane pair (2v, 2v+1): lane bit0 selects z-corner (z0 vs z1). Each lane
// gathers the 4 (y,x) corners at its z, applies weights, then a single
// shfl_xor(1) butterfly combines the pair. This makes the two z-adjacent
// float4 gathers land in the SAME instruction -> same 128B line -> one
// L1 wavefront instead of two.
//
// image: (B=2, H=128, W=128, D=128, C=4) f32
// transformation: (B=2, 128, 128, 128, 3) f32
// out: (B=2, 128, 128, 128, 4) f32

__global__ __launch_bounds__(256) void st3d_kernel(
    const float* __restrict__ img,
    const float* __restrict__ trans,
    float* __restrict__ out,
    int total_threads)
{
    int t = blockIdx.x * blockDim.x + threadIdx.x;
    if (t >= total_threads) return;

    int v  = t >> 1;        // voxel index
    int zs = t & 1;         // 0 -> z0 corner set, 1 -> z1 corner set

    // v = ((b*128 + i)*128 + j)*128 + k   (i:OH/y, j:OW/x, k:OD/z)
    int k = v & 127;
    int j = (v >> 7) & 127;
    int i = (v >> 14) & 127;
    int b = v >> 21;

    const float step = 2.0f / 127.0f;
    float xl = -1.0f + (float)j * step;
    float yl = -1.0f + (float)i * step;
    float zl = -1.0f + (float)k * step;

    const float* tp = trans + (size_t)v * 3;
    float cx = __ldg(&tp[0]) * xl;
    float cy = __ldg(&tp[1]) * yl;
    float cz = __ldg(&tp[2]) * zl;

    float x = 0.5f * (cx + 1.0f) * 128.0f;
    float y = 0.5f * (cy + 1.0f) * 128.0f;
    float z = 0.5f * (cz + 1.0f) * 128.0f;

    int x0 = (int)floorf(x);
    int y0 = (int)floorf(y);
    int z0 = (int)floorf(z);
    int x1 = min(max(x0 + 1, 0), 127);
    int y1 = min(max(y0 + 1, 0), 127);
    int z1 = min(max(z0 + 1, 0), 127);
    x0 = min(max(x0, 0), 127);
    y0 = min(max(y0, 0), 127);
    z0 = min(max(z0, 0), 127);

    float dx = (float)x1 - x;
    float dy = (float)y1 - y;
    float dz = (float)z1 - z;
    float ex = 1.0f - dx;
    float ey = 1.0f - dy;

    // this lane's z corner and z-weight
    int   zi = zs ? z1 : z0;
    float wz = zs ? (1.0f - dz) : dz;

    // image as float4 (C=4): element (b, y, x, z) at b*2097152 + (y<<14 | x<<7 | z)
    const float4* imgb = reinterpret_cast<const float4*>(img) + (size_t)b * 2097152;

    float4 g00 = __ldg(&imgb[(y0 << 14) | (x0 << 7) | zi]);
    float4 g10 = __ldg(&imgb[(y1 << 14) | (x0 << 7) | zi]);
    float4 g01 = __ldg(&imgb[(y0 << 14) | (x1 << 7) | zi]);
    float4 g11 = __ldg(&imgb[(y1 << 14) | (x1 << 7) | zi]);

    float w00 = wz * dx * dy;
    float w10 = wz * dx * ey;
    float w01 = wz * ex * dy;
    float w11 = wz * ex * ey;

    float4 r;
    r.x = w00*g00.x + w10*g10.x + w01*g01.x + w11*g11.x;
    r.y = w00*g00.y + w10*g10.y + w01*g01.y + w11*g11.y;
    r.z = w00*g00.z + w10*g10.z + w01*g01.z + w11*g11.z;
    r.w = w00*g00.w + w10*g10.w + w01*g01.w + w11*g11.w;

    // combine the two z halves across the lane pair
    r.x += __shfl_xor_sync(0xffffffffu, r.x, 1);
    r.y += __shfl_xor_sync(0xffffffffu, r.y, 1);
    r.z += __shfl_xor_sync(0xffffffffu, r.z, 1);
    r.w += __shfl_xor_sync(0xffffffffu, r.w, 1);

    if (zs == 0) {
        reinterpret_cast<float4*>(out)[v] = r;
    }
}

extern "C" void kernel_launch(void* const* d_in, const int* in_sizes, int n_in,
                              void* d_out, int out_size)
{
    const float* img = (const float*)d_in[0];
    const float* trans = (const float*)d_in[1];
    float* out = (float*)d_out;

    int total_threads = (out_size / 4) * 2;  // 2 lanes per voxel
    int threads = 256;
    int blocks = (total_threads + threads - 1) / threads;
    st3d_kernel<<<blocks, threads>>>(img, trans, out, total_threads);
}

// round 3
// speedup vs baseline: 1.4199x; 1.0390x over previous
#include <cuda_runtime.h>

// SpatialTransformer3D: batched 3D trilinear sampling.
// 2 lanes per voxel-z (lane bit0 = z-corner), 2 voxels per thread (even/odd k).
// Per thread: 8 independent float4 gathers (4 corners x 2 voxels at its z),
// pair lanes share 128B lines for the z0/z1 corners within each gather instr.
//
// image: (B=2, H=128, W=128, D=128, C=4) f32
// transformation: (B=2, 128, 128, 128, 3) f32
// out: (B=2, 128, 128, 128, 4) f32

__global__ __launch_bounds__(256, 4) void st3d_kernel(
    const float* __restrict__ img,
    const float* __restrict__ trans,
    float* __restrict__ out,
    int total_threads)
{
    int t = blockIdx.x * blockDim.x + threadIdx.x;
    if (t >= total_threads) return;

    int zs = t & 1;          // 0 -> z0 corner set, 1 -> z1 corner set
    int q  = t >> 1;         // voxel-pair index: voxels v0 = 2q, v0+1
    int v0 = q << 1;

    // v0 = ((b*128 + i)*128 + j)*128 + k0, k0 even -> voxel pair shares b,i,j
    int k0 = v0 & 127;
    int j  = (v0 >> 7) & 127;
    int i  = (v0 >> 14) & 127;
    int b  = v0 >> 21;

    const float step = 2.0f / 127.0f;
    float xl  = -1.0f + (float)j * step;
    float yl  = -1.0f + (float)i * step;
    float zlA = -1.0f + (float)k0 * step;
    float zlB = zlA + step;

    // 6 transform floats for the voxel pair: 24 contiguous bytes, 8B-aligned
    const float2* tp = reinterpret_cast<const float2*>(trans) + (size_t)q * 3;
    float2 fa = __ldg(&tp[0]);   // txA, tyA
    float2 fb = __ldg(&tp[1]);   // tzA, txB
    float2 fc = __ldg(&tp[2]);   // tyB, tzB

    const float4* imgb = reinterpret_cast<const float4*>(img) + (size_t)b * 2097152;

    float4 rA, rB;

    // ---- voxel A ----
    {
        float x = 0.5f * (fa.x * xl + 1.0f) * 128.0f;
        float y = 0.5f * (fa.y * yl + 1.0f) * 128.0f;
        float z = 0.5f * (fb.x * zlA + 1.0f) * 128.0f;

        int x0 = (int)floorf(x), y0 = (int)floorf(y), z0 = (int)floorf(z);
        int x1 = min(max(x0 + 1, 0), 127);
        int y1 = min(max(y0 + 1, 0), 127);
        int z1 = min(max(z0 + 1, 0), 127);
        x0 = min(max(x0, 0), 127);
        y0 = min(max(y0, 0), 127);
        z0 = min(max(z0, 0), 127);

        float dx = (float)x1 - x, dy = (float)y1 - y, dz = (float)z1 - z;
        float ex = 1.0f - dx, ey = 1.0f - dy;

        int   zi = zs ? z1 : z0;
        float wz = zs ? (1.0f - dz) : dz;

        float4 g00 = __ldg(&imgb[(y0 << 14) | (x0 << 7) | zi]);
        float4 g10 = __ldg(&imgb[(y1 << 14) | (x0 << 7) | zi]);
        float4 g01 = __ldg(&imgb[(y0 << 14) | (x1 << 7) | zi]);
        float4 g11 = __ldg(&imgb[(y1 << 14) | (x1 << 7) | zi]);

        float w00 = wz * dx * dy, w10 = wz * dx * ey;
        float w01 = wz * ex * dy, w11 = wz * ex * ey;

        rA.x = w00*g00.x + w10*g10.x + w01*g01.x + w11*g11.x;
        rA.y = w00*g00.y + w10*g10.y + w01*g01.y + w11*g11.y;
        rA.z = w00*g00.z + w10*g10.z + w01*g01.z + w11*g11.z;
        rA.w = w00*g00.w + w10*g10.w + w01*g01.w + w11*g11.w;
    }

    // ---- voxel B ----
    {
        float x = 0.5f * (fb.y * xl + 1.0f) * 128.0f;
        float y = 0.5f * (fc.x * yl + 1.0f) * 128.0f;
        float z = 0.5f * (fc.y * zlB + 1.0f) * 128.0f;

        int x0 = (int)floorf(x), y0 = (int)floorf(y), z0 = (int)floorf(z);
        int x1 = min(max(x0 + 1, 0), 127);
        int y1 = min(max(y0 + 1, 0), 127);
        int z1 = min(max(z0 + 1, 0), 127);
        x0 = min(max(x0, 0), 127);
        y0 = min(max(y0, 0), 127);
        z0 = min(max(z0, 0), 127);

        float dx = (float)x1 - x, dy = (float)y1 - y, dz = (float)z1 - z;
        float ex = 1.0f - dx, ey = 1.0f - dy;

        int   zi = zs ? z1 : z0;
        float wz = zs ? (1.0f - dz) : dz;

        float4 g00 = __ldg(&imgb[(y0 << 14) | (x0 << 7) | zi]);
        float4 g10 = __ldg(&imgb[(y1 << 14) | (x0 << 7) | zi]);
        float4 g01 = __ldg(&imgb[(y0 << 14) | (x1 << 7) | zi]);
        float4 g11 = __ldg(&imgb[(y1 << 14) | (x1 << 7) | zi]);

        float w00 = wz * dx * dy, w10 = wz * dx * ey;
        float w01 = wz * ex * dy, w11 = wz * ex * ey;

        rB.x = w00*g00.x + w10*g10.x + w01*g01.x + w11*g11.x;
        rB.y = w00*g00.y + w10*g10.y + w01*g01.y + w11*g11.y;
        rB.z = w00*g00.z + w10*g10.z + w01*g01.z + w11*g11.z;
        rB.w = w00*g00.w + w10*g10.w + w01*g01.w + w11*g11.w;
    }

    // combine z halves across the lane pair (both voxels)
    rA.x += __shfl_xor_sync(0xffffffffu, rA.x, 1);
    rA.y += __shfl_xor_sync(0xffffffffu, rA.y, 1);
    rA.z += __shfl_xor_sync(0xffffffffu, rA.z, 1);
    rA.w += __shfl_xor_sync(0xffffffffu, rA.w, 1);
    rB.x += __shfl_xor_sync(0xffffffffu, rB.x, 1);
    rB.y += __shfl_xor_sync(0xffffffffu, rB.y, 1);
    rB.z += __shfl_xor_sync(0xffffffffu, rB.z, 1);
    rB.w += __shfl_xor_sync(0xffffffffu, rB.w, 1);

    // even lane stores voxel v0, odd lane stores v0+1 -> dense float4 store
    float4 r = zs ? rB : rA;
    reinterpret_cast<float4*>(out)[v0 + zs] = r;
}

extern "C" void kernel_launch(void* const* d_in, const int* in_sizes, int n_in,
                              void* d_out, int out_size)
{
    const float* img = (const float*)d_in[0];
    const float* trans = (const float*)d_in[1];
    float* out = (float*)d_out;

    int total_threads = out_size / 4;  // one thread per voxel (2 voxels x half-z each)
    int threads = 256;
    int blocks = (total_threads + threads - 1) / threads;
    st3d_kernel<<<blocks, threads>>>(img, trans, out, total_threads);
}

// round 4
// speedup vs baseline: 1.4691x; 1.0346x over previous
#include <cuda_runtime.h>

// SpatialTransformer3D: batched 3D trilinear sampling.
// 2 lanes per voxel (lane bit0 = z-corner), 2 voxels per thread (even/odd k).
// All 8 float4 gathers are address-computed first, then issued back-to-back
// for maximum MLP. Lane pairs share 128B lines on the z0/z1 corner pairs.
//
// image: (B=2, H=128, W=128, D=128, C=4) f32
// transformation: (B=2, 128, 128, 128, 3) f32
// out: (B=2, 128, 128, 128, 4) f32

__global__ __launch_bounds__(256) void st3d_kernel(
    const float* __restrict__ img,
    const float* __restrict__ trans,
    float* __restrict__ out)
{
    int t = blockIdx.x * blockDim.x + threadIdx.x;

    int zs = t & 1;          // 0 -> z0 corner set, 1 -> z1 corner set
    int q  = t >> 1;         // voxel-pair index: voxels v0 = 2q, v0+1
    int v0 = q << 1;

    // v0 = ((b*128 + i)*128 + j)*128 + k0, k0 even -> pair shares b,i,j
    int k0 = v0 & 127;
    int j  = (v0 >> 7) & 127;
    int i  = (v0 >> 14) & 127;
    int b  = v0 >> 21;

    const float step = 2.0f / 127.0f;
    float xl  = -1.0f + (float)j * step;
    float yl  = -1.0f + (float)i * step;
    float zlA = -1.0f + (float)k0 * step;
    float zlB = zlA + step;

    // 6 transform floats for the voxel pair: 24 contiguous bytes, 8B-aligned
    const float2* tp = reinterpret_cast<const float2*>(trans) + (size_t)q * 3;
    float2 fa = __ldg(&tp[0]);   // txA, tyA
    float2 fb = __ldg(&tp[1]);   // tzA, txB
    float2 fc = __ldg(&tp[2]);   // tyB, tzB

    const float4* imgb = reinterpret_cast<const float4*>(img) + (size_t)b * 2097152;

    // ---- voxel A address/weight setup ----
    float xA = 0.5f * (fa.x * xl + 1.0f) * 128.0f;
    float yA = 0.5f * (fa.y * yl + 1.0f) * 128.0f;
    float zA = 0.5f * (fb.x * zlA + 1.0f) * 128.0f;

    int x0A = (int)floorf(xA), y0A = (int)floorf(yA), z0A = (int)floorf(zA);
    int x1A = min(max(x0A + 1, 0), 127);
    int y1A = min(max(y0A + 1, 0), 127);
    int z1A = min(max(z0A + 1, 0), 127);
    x0A = min(max(x0A, 0), 127);
    y0A = min(max(y0A, 0), 127);
    z0A = min(max(z0A, 0), 127);

    float dxA = (float)x1A - xA, dyA = (float)y1A - yA, dzA = (float)z1A - zA;
    int   ziA = zs ? z1A : z0A;
    float wzA = zs ? (1.0f - dzA) : dzA;

    // ---- voxel B address/weight setup ----
    float xB = 0.5f * (fb.y * xl + 1.0f) * 128.0f;
    float yB = 0.5f * (fc.x * yl + 1.0f) * 128.0f;
    float zB = 0.5f * (fc.y * zlB + 1.0f) * 128.0f;

    int x0B = (int)floorf(xB), y0B = (int)floorf(yB), z0B = (int)floorf(zB);
    int x1B = min(max(x0B + 1, 0), 127);
    int y1B = min(max(y0B + 1, 0), 127);
    int z1B = min(max(z0B + 1, 0), 127);
    x0B = min(max(x0B, 0), 127);
    y0B = min(max(y0B, 0), 127);
    z0B = min(max(z0B, 0), 127);

    float dxB = (float)x1B - xB, dyB = (float)y1B - yB, dzB = (float)z1B - zB;
    int   ziB = zs ? z1B : z0B;
    float wzB = zs ? (1.0f - dzB) : dzB;

    // ---- issue all 8 gathers back-to-back ----
    float4 a00 = __ldg(&imgb[(y0A << 14) | (x0A << 7) | ziA]);
    float4 a10 = __ldg(&imgb[(y1A << 14) | (x0A << 7) | ziA]);
    float4 a01 = __ldg(&imgb[(y0A << 14) | (x1A << 7) | ziA]);
    float4 a11 = __ldg(&imgb[(y1A << 14) | (x1A << 7) | ziA]);
    float4 b00 = __ldg(&imgb[(y0B << 14) | (x0B << 7) | ziB]);
    float4 b10 = __ldg(&imgb[(y1B << 14) | (x0B << 7) | ziB]);
    float4 b01 = __ldg(&imgb[(y0B << 14) | (x1B << 7) | ziB]);
    float4 b11 = __ldg(&imgb[(y1B << 14) | (x1B << 7) | ziB]);

    float exA = 1.0f - dxA, eyA = 1.0f - dyA;
    float w00A = wzA * dxA * dyA, w10A = wzA * dxA * eyA;
    float w01A = wzA * exA * dyA, w11A = wzA * exA * eyA;

    float exB = 1.0f - dxB, eyB = 1.0f - dyB;
    float w00B = wzB * dxB * dyB, w10B = wzB * dxB * eyB;
    float w01B = wzB * exB * dyB, w11B = wzB * exB * eyB;

    float4 rA, rB;
    rA.x = w00A*a00.x + w10A*a10.x + w01A*a01.x + w11A*a11.x;
    rA.y = w00A*a00.y + w10A*a10.y + w01A*a01.y + w11A*a11.y;
    rA.z = w00A*a00.z + w10A*a10.z + w01A*a01.z + w11A*a11.z;
    rA.w = w00A*a00.w + w10A*a10.w + w01A*a01.w + w11A*a11.w;
    rB.x = w00B*b00.x + w10B*b10.x + w01B*b01.x + w11B*b11.x;
    rB.y = w00B*b00.y + w10B*b10.y + w01B*b01.y + w11B*b11.y;
    rB.z = w00B*b00.z + w10B*b10.z + w01B*b01.z + w11B*b11.z;
    rB.w = w00B*b00.w + w10B*b10.w + w01B*b01.w + w11B*b11.w;

    // combine z halves across the lane pair (both voxels)
    rA.x += __shfl_xor_sync(0xffffffffu, rA.x, 1);
    rA.y += __shfl_xor_sync(0xffffffffu, rA.y, 1);
    rA.z += __shfl_xor_sync(0xffffffffu, rA.z, 1);
    rA.w += __shfl_xor_sync(0xffffffffu, rA.w, 1);
    rB.x += __shfl_xor_sync(0xffffffffu, rB.x, 1);
    rB.y += __shfl_xor_sync(0xffffffffu, rB.y, 1);
    rB.z += __shfl_xor_sync(0xffffffffu, rB.z, 1);
    rB.w += __shfl_xor_sync(0xffffffffu, rB.w, 1);

    // even lane stores voxel v0, odd lane stores v0+1 -> dense float4 store
    float4 r = zs ? rB : rA;
    reinterpret_cast<float4*>(out)[v0 + zs] = r;
}

extern "C" void kernel_launch(void* const* d_in, const int* in_sizes, int n_in,
                              void* d_out, int out_size)
{
    const float* img = (const float*)d_in[0];
    const float* trans = (const float*)d_in[1];
    float* out = (float*)d_out;

    int total_threads = out_size / 4;  // 4.19M: one thread per voxel role
    int threads = 256;
    int blocks = total_threads / threads;  // divides exactly (16384)
    st3d_kernel<<<blocks, threads>>>(img, trans, out);
}